// round 1
// baseline (speedup 1.0000x reference)
#include <cuda_runtime.h>
#include <cstdint>

// ---------------- problem constants ----------------
#define NB   16
#define CC   64
#define TT   30
#define HH   64
#define WW   44
#define PC   64
#define OUTH 16
#define OUTW 20
#define AOUTH 16            // round(OUT_W / (40/32)) == 16 == OUTH -> zero pad
#define PQ   (OUTH*OUTW)    // 320
#define CT   (CC*TT)        // 1920
#define HW   (HH*WW)        // 2816
#define OUT_MAIN (NB*CC*TT*PQ)   // 9,830,400
#define OUT_TOTAL (OUT_MAIN + 7*NB)

// derived scalar constants (exact from reference):
// atten_in_t=12, atten_in_h=32, atten_in_w=40, anchor_t=15, anchor_x=22, anchor_y=24
#define W_RATE (10.0f/11.0f)
#define T_RATE 0.4f

// ---------------- device scratch (static, allocation-free) ----------------
__device__ float g_scratch[(size_t)NB*CT*PQ];      // 39.3 MB
__device__ float d_Fx[NB*OUTW*WW];                 // [n][q][w]
__device__ float d_Fy[NB*AOUTH*HH];                // [n][p][h]
__device__ float d_gamma[NB];
__device__ int   d_i0c[NB*TT];
__device__ int   d_i1c[NB*TT];
__device__ float d_w0[NB*TT];
__device__ float d_w1[NB*TT];

// ---------------- kernel 1: MLP + params + filter banks ----------------
__global__ void setup_kernel(const float* __restrict__ px,
                             const float* __restrict__ W1, const float* __restrict__ b1,
                             const float* __restrict__ W2, const float* __restrict__ b2,
                             float* __restrict__ out, int write_params) {
    __shared__ float hid[NB*32];
    __shared__ float pp[NB*7];
    __shared__ float sdx[NB], sdy[NB], ss2[NB], sdel[NB], sdt[NB], sdelt[NB];
    int tid = threadIdx.x;  // 512 threads

    // hid = tanh(param_x @ W1 + b1)
    {
        int n = tid >> 5, j = tid & 31;
        float acc = b1[j];
        #pragma unroll 8
        for (int i = 0; i < PC; i++) acc += px[n*PC + i] * W1[i*32 + j];
        hid[n*32 + j] = tanhf(acc);
    }
    __syncthreads();

    // p = hid @ W2 + b2  (16x7)
    if (tid < NB*7) {
        int n = tid / 7, m = tid % 7;
        float acc = b2[m];
        #pragma unroll
        for (int j = 0; j < 32; j++) acc += hid[n*32 + j] * W2[j*7 + m];
        pp[n*7 + m] = acc;
    }
    __syncthreads();

    if (tid < NB) {
        int n = tid;
        float dt0 = pp[n*7+0], dx0 = pp[n*7+1], dy0 = pp[n*7+2];
        float ls2 = pp[n*7+3], ldt = pp[n*7+4], ldl = pp[n*7+5], lg = pp[n*7+6];
        float dx    = tanhf(dx0) * 20.0f + 22.0f;   // atten_in_w/2 + anchor_x
        float dy    = tanhf(dy0) * 16.0f + 24.0f;   // atten_in_h/2 + anchor_y
        float s2    = expf(ls2);
        float delta = expf(ldl) * W_RATE;
        float gamma = 1.0f / (1.0f + expf(-lg));
        float dt    = tanhf(dt0) * 6.0f + 15.0f;    // atten_in_t/2 + anchor_t
        float dlt   = expf(ldt) * T_RATE;
        sdx[n] = dx; sdy[n] = dy; ss2[n] = s2; sdel[n] = delta;
        sdt[n] = dt; sdelt[n] = dlt;
        d_gamma[n] = gamma;
        if (write_params) {
            out[OUT_MAIN + 0*NB + n] = dt;
            out[OUT_MAIN + 1*NB + n] = dx;
            out[OUT_MAIN + 2*NB + n] = dy;
            out[OUT_MAIN + 3*NB + n] = s2;
            out[OUT_MAIN + 4*NB + n] = delta;
            out[OUT_MAIN + 5*NB + n] = dlt;
            out[OUT_MAIN + 6*NB + n] = gamma;
        }
    }
    __syncthreads();

    // Fx rows: 16*20 = 320 rows of 44
    if (tid < NB*OUTW) {
        int n = tid / OUTW, q = tid % OUTW;
        float mu = sdx[n] + ((float)q - 10.0f) * sdel[n];
        float inv2s = 1.0f / (2.0f * ss2[n]);
        float vals[WW]; float sum = 0.0f;
        #pragma unroll
        for (int w = 0; w < WW; w++) {
            float d = (float)w - mu;
            float v = expf(-d*d*inv2s);
            vals[w] = v; sum += v;
        }
        float inv = 1.0f / fmaxf(sum, 1e-8f);
        #pragma unroll
        for (int w = 0; w < WW; w++) d_Fx[n*(OUTW*WW) + q*WW + w] = vals[w] * inv;
    }

    // Fy rows: 16*16 = 256 rows of 64
    if (tid < NB*AOUTH) {
        int n = tid / AOUTH, p = tid % AOUTH;
        float mu = sdy[n] + ((float)p - 8.0f) * sdel[n];
        float inv2s = 1.0f / (2.0f * ss2[n]);
        float sum = 0.0f;
        float vals[HH];
        #pragma unroll
        for (int h = 0; h < HH; h++) {
            float d = (float)h - mu;
            float v = expf(-d*d*inv2s);
            vals[h] = v; sum += v;
        }
        float inv = 1.0f / fmaxf(sum, 1e-8f);
        #pragma unroll
        for (int h = 0; h < HH; h++) d_Fy[n*(AOUTH*HH) + p*HH + h] = vals[h] * inv;
    }

    // temporal weights: 16*30 = 480
    if (tid < NB*TT) {
        int n = tid / TT, k = tid % TT;
        float mu = sdt[n] + ((float)k - 15.0f) * sdelt[n];
        float fl = floorf(mu);
        float frac = mu - fl;
        int i0 = (int)fl;
        int i1 = i0 + 1;
        d_w0[tid] = (i0 >= 0 && i0 < TT) ? (1.0f - frac) : 0.0f;
        d_w1[tid] = (i1 >= 0 && i1 < TT) ? frac : 0.0f;
        d_i0c[tid] = min(max(i0, 0), TT-1);
        d_i1c[tid] = min(max(i1, 0), TT-1);
    }
}

// ---------------- kernel 2: spatial attention g = Fy @ (x @ Fx^T) ----------------
// one block per (n, c*t); 320 threads
__global__ void __launch_bounds__(320) spatial_kernel(const float* __restrict__ x) {
    __shared__ float xs[HW];              // 2816
    __shared__ float fxs[OUTW*WW];        // 880
    __shared__ float fys[AOUTH*HH];       // 1024
    __shared__ float t1s[HH*21];          // 64 x 20 padded to 21

    int n  = blockIdx.y;
    int ct = blockIdx.x;
    int tid = threadIdx.x;

    const float* xp = x + ((size_t)n*CT + ct) * HW;
    for (int i = tid; i < HW; i += 320)        xs[i]  = xp[i];
    for (int i = tid; i < OUTW*WW; i += 320)   fxs[i] = d_Fx[n*(OUTW*WW) + i];
    for (int i = tid; i < AOUTH*HH; i += 320)  fys[i] = d_Fy[n*(AOUTH*HH) + i];
    __syncthreads();

    // phase 1: t1[h][q] = sum_w x[h][w] * Fx[q][w]   (1280 outputs / 320 thr -> 4 each)
    #pragma unroll
    for (int r = 0; r < 4; r++) {
        int idx = tid + r*320;
        int h = idx / OUTW, q = idx % OUTW;
        const float* xr = &xs[h*WW];
        const float* fr = &fxs[q*WW];
        float acc = 0.0f;
        #pragma unroll
        for (int w = 0; w < WW; w++) acc += xr[w] * fr[w];
        t1s[h*21 + q] = acc;
    }
    __syncthreads();

    // phase 2: g[p][q] = sum_h Fy[p][h] * t1[h][q]   (320 outputs, 1 each)
    int p = tid / OUTW, q = tid % OUTW;
    float acc = 0.0f;
    #pragma unroll
    for (int h = 0; h < HH; h++) acc += fys[p*HH + h] * t1s[h*21 + q];
    g_scratch[((size_t)n*CT + ct) * PQ + tid] = acc;
}

// ---------------- kernel 3: temporal lerp + gamma + channel mix GEMM ----------------
// grid (4 spatial quarters, T, N); 320 threads; each block: out[n, :, k, quarter] = Wf @ S + bf
__global__ void __launch_bounds__(320) mix_kernel(const float* __restrict__ Wf,
                                                  const float* __restrict__ bf,
                                                  float* __restrict__ out) {
    __shared__ float wfs[CC*CC];      // 4096
    __shared__ float S[CC*80];        // 5120 : sampled * gamma, [c][s]
    __shared__ float bfs[CC];

    int quarter = blockIdx.x;   // 0..3 -> pq offset quarter*80
    int k = blockIdx.y;         // 0..29
    int n = blockIdx.z;         // 0..15
    int tid = threadIdx.x;

    for (int i = tid; i < CC*CC; i += 320) wfs[i] = Wf[i];
    if (tid < CC) bfs[tid] = bf[tid];

    int   i0 = d_i0c[n*TT + k];
    int   i1 = d_i1c[n*TT + k];
    float w0 = d_w0[n*TT + k];
    float w1 = d_w1[n*TT + k];
    float gm = d_gamma[n];

    // load S[c][s] = gamma * (w0*g[n,c,i0,pq] + w1*g[n,c,i1,pq])
    #pragma unroll
    for (int r = 0; r < 16; r++) {
        int e = tid + r*320;         // 0..5119
        int c = e / 80, s = e % 80;
        size_t base = ((size_t)(n*CC + c) * TT) * PQ + quarter*80 + s;
        float v0 = g_scratch[base + (size_t)i0 * PQ];
        float v1 = g_scratch[base + (size_t)i1 * PQ];
        S[e] = gm * (w0*v0 + w1*v1);
    }
    __syncthreads();

    // out[o][s] = sum_c Wf[o][c] * S[c][s] + bf[o]
    int s  = tid % 80;
    int og = tid / 80;   // 0..3 -> o in [og*16, og*16+16)
    float acc[16];
    #pragma unroll
    for (int oo = 0; oo < 16; oo++) acc[oo] = 0.0f;
    for (int c = 0; c < CC; c++) {
        float sv = S[c*80 + s];
        #pragma unroll
        for (int oo = 0; oo < 16; oo++)
            acc[oo] += wfs[(og*16 + oo)*CC + c] * sv;
    }
    #pragma unroll
    for (int oo = 0; oo < 16; oo++) {
        int o = og*16 + oo;
        out[(((size_t)n*CC + o)*TT + k) * PQ + quarter*80 + s] = acc[oo] + bfs[o];
    }
}

// ---------------- launch ----------------
extern "C" void kernel_launch(void* const* d_in, const int* in_sizes, int n_in,
                              void* d_out, int out_size) {
    const float* x   = (const float*)d_in[0];
    const float* px  = (const float*)d_in[1];
    const float* W1  = (const float*)d_in[2];
    const float* b1  = (const float*)d_in[3];
    const float* W2  = (const float*)d_in[4];
    const float* b2  = (const float*)d_in[5];
    const float* Wf  = (const float*)d_in[6];
    const float* bf  = (const float*)d_in[7];
    float* out = (float*)d_out;

    int write_params = (out_size >= OUT_TOTAL) ? 1 : 0;

    setup_kernel<<<1, 512>>>(px, W1, b1, W2, b2, out, write_params);

    dim3 g2(CT, NB);
    spatial_kernel<<<g2, 320>>>(x);

    dim3 g3(4, TT, NB);
    mix_kernel<<<g3, 320>>>(Wf, bf, out);
}

// round 2
// speedup vs baseline: 1.6127x; 1.6127x over previous
#include <cuda_runtime.h>
#include <cstdint>

// ---------------- problem constants ----------------
#define NB   16
#define CC   64
#define TT   30
#define HH   64
#define WW   44
#define PC   64
#define OUTH 16
#define OUTW 20
#define AOUTH 16            // round(OUT_W / (40/32)) == 16 == OUTH -> zero pad
#define PQ   (OUTH*OUTW)    // 320
#define CT   (CC*TT)        // 1920
#define HW   (HH*WW)        // 2816
#define OUT_MAIN (NB*CC*TT*PQ)   // 9,830,400
#define OUT_TOTAL (OUT_MAIN + 7*NB)

#define W_RATE (10.0f/11.0f)
#define T_RATE 0.4f

#define SP1 45   // padded xs row stride (bank-conflict-free scalar loads)
#define SP2 68   // padded t1T / fys row stride (float4-aligned)

// ---------------- device scratch (static, allocation-free) ----------------
__device__ float g_scratch[(size_t)NB*CT*PQ];      // 39.3 MB
__device__ float d_Fx[NB*OUTW*WW];                 // [n][q][w]
__device__ float d_Fy[NB*AOUTH*HH];                // [n][p][h]
__device__ float d_gamma[NB];
__device__ int   d_i0c[NB*TT];
__device__ int   d_i1c[NB*TT];
__device__ float d_w0[NB*TT];
__device__ float d_w1[NB*TT];

// ---------------- kernel 1: MLP + params + filter banks ----------------
__global__ void setup_kernel(const float* __restrict__ px,
                             const float* __restrict__ W1, const float* __restrict__ b1,
                             const float* __restrict__ W2, const float* __restrict__ b2,
                             float* __restrict__ out, int write_params) {
    __shared__ float hid[NB*32];
    __shared__ float pp[NB*7];
    __shared__ float sdx[NB], sdy[NB], ss2[NB], sdel[NB], sdt[NB], sdelt[NB];
    int tid  = threadIdx.x;  // 512 threads, 16 warps
    int lane = tid & 31;
    int wrp  = tid >> 5;

    // hid = tanh(param_x @ W1 + b1)
    {
        int n = tid >> 5, j = tid & 31;
        float acc = b1[j];
        #pragma unroll 8
        for (int i = 0; i < PC; i++) acc += px[n*PC + i] * W1[i*32 + j];
        hid[n*32 + j] = tanhf(acc);
    }
    __syncthreads();

    // p = hid @ W2 + b2  (16x7)
    if (tid < NB*7) {
        int n = tid / 7, m = tid % 7;
        float acc = b2[m];
        #pragma unroll
        for (int j = 0; j < 32; j++) acc += hid[n*32 + j] * W2[j*7 + m];
        pp[n*7 + m] = acc;
    }
    __syncthreads();

    if (tid < NB) {
        int n = tid;
        float dt0 = pp[n*7+0], dx0 = pp[n*7+1], dy0 = pp[n*7+2];
        float ls2 = pp[n*7+3], ldt = pp[n*7+4], ldl = pp[n*7+5], lg = pp[n*7+6];
        float dx    = tanhf(dx0) * 20.0f + 22.0f;   // atten_in_w/2 + anchor_x
        float dy    = tanhf(dy0) * 16.0f + 24.0f;   // atten_in_h/2 + anchor_y
        float s2    = expf(ls2);
        float delta = expf(ldl) * W_RATE;
        float gamma = 1.0f / (1.0f + expf(-lg));
        float dt    = tanhf(dt0) * 6.0f + 15.0f;    // atten_in_t/2 + anchor_t
        float dlt   = expf(ldt) * T_RATE;
        sdx[n] = dx; sdy[n] = dy; ss2[n] = s2; sdel[n] = delta;
        sdt[n] = dt; sdelt[n] = dlt;
        d_gamma[n] = gamma;
        if (write_params) {
            out[OUT_MAIN + 0*NB + n] = dt;
            out[OUT_MAIN + 1*NB + n] = dx;
            out[OUT_MAIN + 2*NB + n] = dy;
            out[OUT_MAIN + 3*NB + n] = s2;
            out[OUT_MAIN + 4*NB + n] = delta;
            out[OUT_MAIN + 5*NB + n] = dlt;
            out[OUT_MAIN + 6*NB + n] = gamma;
        }
    }

    // temporal weights: 16*30 = 480 (needs sdt/sdelt -> after sync below; but
    // sdt written by tid<16 which is same sync domain, so do after syncthreads)
    __syncthreads();

    if (tid < NB*TT) {
        int n = tid / TT, k = tid % TT;
        float mu = sdt[n] + ((float)k - 15.0f) * sdelt[n];
        float fl = floorf(mu);
        float frac = mu - fl;
        int i0 = (int)fl;
        int i1 = i0 + 1;
        d_w0[tid] = (i0 >= 0 && i0 < TT) ? (1.0f - frac) : 0.0f;
        d_w1[tid] = (i1 >= 0 && i1 < TT) ? frac : 0.0f;
        d_i0c[tid] = min(max(i0, 0), TT-1);
        d_i1c[tid] = min(max(i1, 0), TT-1);
    }

    // filter rows: warp-per-row with shfl reduction.
    // rows 0..319  -> Fx (n = r/20, q = r%20), len 44
    // rows 320..575 -> Fy (n = (r-320)/16, p = %16), len 64
    for (int row = wrp; row < 576; row += 16) {
        float mu, inv2s, *dst;
        int len;
        if (row < 320) {
            int n = row / OUTW, q = row - n*OUTW;
            mu = sdx[n] + ((float)q - 10.0f) * sdel[n];
            inv2s = 1.0f / (2.0f * ss2[n]);
            len = WW;
            dst = &d_Fx[n*(OUTW*WW) + q*WW];
        } else {
            int r2 = row - 320;
            int n = r2 / AOUTH, p = r2 - n*AOUTH;
            mu = sdy[n] + ((float)p - 8.0f) * sdel[n];
            inv2s = 1.0f / (2.0f * ss2[n]);
            len = HH;
            dst = &d_Fy[n*(AOUTH*HH) + p*HH];
        }
        float d0 = (float)lane - mu;
        float d1 = (float)(lane + 32) - mu;
        float v0 = (lane      < len) ? expf(-d0*d0*inv2s) : 0.0f;
        float v1 = (lane + 32 < len) ? expf(-d1*d1*inv2s) : 0.0f;
        float s = v0 + v1;
        #pragma unroll
        for (int o = 16; o > 0; o >>= 1) s += __shfl_xor_sync(0xffffffffu, s, o);
        float inv = 1.0f / fmaxf(s, 1e-8f);
        if (lane      < len) dst[lane]      = v0 * inv;
        if (lane + 32 < len) dst[lane + 32] = v1 * inv;
    }
}

// ---------------- kernel 2: spatial attention g = Fy @ (x @ Fx^T) ----------------
// 2 (c,t)-tiles per block, 160 threads (80 per tile), 4x4 register tiling.
__global__ void __launch_bounds__(160) spatial_kernel(const float* __restrict__ x) {
    __shared__ float xs[2][HH*SP1];         // 2*2880
    __shared__ float fxT[WW*OUTW];          // [w][q], 880
    __shared__ float fys[AOUTH*SP2];        // [p][h], padded
    __shared__ float t1T[2][OUTW*SP2];      // [q][h], padded

    int n   = blockIdx.y;
    int ct0 = blockIdx.x * 2;
    int tid = threadIdx.x;

    // stage x (two contiguous tiles)
    const float* xp = x + ((size_t)n*CT + ct0) * HW;
    for (int i = tid; i < 2*HW; i += 160) {
        int tile = i / HW;
        int e = i - tile*HW;
        int h = e / WW, w = e - h*WW;
        xs[tile][h*SP1 + w] = xp[i];
    }
    // stage Fx transposed [w][q]
    for (int i = tid; i < OUTW*WW; i += 160) {
        int q = i / WW, w = i - q*WW;
        fxT[w*OUTW + q] = d_Fx[n*(OUTW*WW) + i];
    }
    // stage Fy padded [p][SP2]
    for (int i = tid; i < AOUTH*HH; i += 160) {
        int p = i >> 6, h = i & 63;
        fys[p*SP2 + h] = d_Fy[n*(AOUTH*HH) + i];
    }
    __syncthreads();

    int tile = tid / 80;
    int t    = tid - tile*80;

    // phase 1: t1[h][q] = sum_w x[h][w] * Fx[q][w]; thread owns 4h x 4q
    {
        int qt = t % 5, ht = t / 5;     // 5 q-groups share x rows (broadcast)
        int h0 = ht * 4, q0 = qt * 4;
        float acc[4][4];
        #pragma unroll
        for (int r = 0; r < 4; r++)
            #pragma unroll
            for (int s = 0; s < 4; s++) acc[r][s] = 0.0f;

        const float* xr = &xs[tile][h0*SP1];
        #pragma unroll
        for (int w = 0; w < WW; w++) {
            float4 b = *(const float4*)&fxT[w*OUTW + q0];
            float a0 = xr[w];
            float a1 = xr[SP1 + w];
            float a2 = xr[2*SP1 + w];
            float a3 = xr[3*SP1 + w];
            acc[0][0] += a0*b.x; acc[0][1] += a0*b.y; acc[0][2] += a0*b.z; acc[0][3] += a0*b.w;
            acc[1][0] += a1*b.x; acc[1][1] += a1*b.y; acc[1][2] += a1*b.z; acc[1][3] += a1*b.w;
            acc[2][0] += a2*b.x; acc[2][1] += a2*b.y; acc[2][2] += a2*b.z; acc[2][3] += a2*b.w;
            acc[3][0] += a3*b.x; acc[3][1] += a3*b.y; acc[3][2] += a3*b.z; acc[3][3] += a3*b.w;
        }
        #pragma unroll
        for (int s = 0; s < 4; s++)
            #pragma unroll
            for (int r = 0; r < 4; r++)
                t1T[tile][(q0 + s)*SP2 + h0 + r] = acc[r][s];
    }
    __syncthreads();

    // phase 2: g[p][q] = sum_h Fy[p][h] * t1[h][q]; thread owns 2p x 2q
    {
        int pt = t / 10, qt2 = t - pt*10;
        int p0 = pt * 2, q0 = qt2 * 2;
        float d00 = 0.f, d01 = 0.f, d10 = 0.f, d11 = 0.f;
        #pragma unroll
        for (int h = 0; h < HH; h += 4) {
            float4 f0 = *(const float4*)&fys[p0*SP2 + h];
            float4 f1 = *(const float4*)&fys[(p0+1)*SP2 + h];
            float4 u0 = *(const float4*)&t1T[tile][q0*SP2 + h];
            float4 u1 = *(const float4*)&t1T[tile][(q0+1)*SP2 + h];
            d00 += f0.x*u0.x + f0.y*u0.y + f0.z*u0.z + f0.w*u0.w;
            d01 += f0.x*u1.x + f0.y*u1.y + f0.z*u1.z + f0.w*u1.w;
            d10 += f1.x*u0.x + f1.y*u0.y + f1.z*u0.z + f1.w*u0.w;
            d11 += f1.x*u1.x + f1.y*u1.y + f1.z*u1.z + f1.w*u1.w;
        }
        size_t base = ((size_t)n*CT + ct0 + tile) * PQ;
        g_scratch[base +  p0   *OUTW + q0    ] = d00;
        g_scratch[base +  p0   *OUTW + q0 + 1] = d01;
        g_scratch[base + (p0+1)*OUTW + q0    ] = d10;
        g_scratch[base + (p0+1)*OUTW + q0 + 1] = d11;
    }
}

// ---------------- kernel 3: temporal lerp + gamma + channel mix GEMM ----------------
__global__ void __launch_bounds__(320) mix_kernel(const float* __restrict__ Wf,
                                                  const float* __restrict__ bf,
                                                  float* __restrict__ out) {
    __shared__ float wfs[CC*CC];      // 4096
    __shared__ float S[CC*80];        // [c][s]
    __shared__ float bfs[CC];

    int quarter = blockIdx.x;   // 0..3 -> pq offset quarter*80
    int k = blockIdx.y;         // 0..29
    int n = blockIdx.z;         // 0..15
    int tid = threadIdx.x;

    for (int i = tid; i < CC*CC; i += 320) wfs[i] = Wf[i];
    if (tid < CC) bfs[tid] = bf[tid];

    int   i0 = d_i0c[n*TT + k];
    int   i1 = d_i1c[n*TT + k];
    float w0 = d_w0[n*TT + k];
    float w1 = d_w1[n*TT + k];
    float gm = d_gamma[n];

    // S[c][s] = gamma * (w0*g[n,c,i0,pq] + w1*g[n,c,i1,pq])
    #pragma unroll
    for (int r = 0; r < 16; r++) {
        int e = tid + r*320;         // 0..5119
        int c = e / 80, s = e - c*80;
        size_t base = ((size_t)(n*CC + c) * TT) * PQ + quarter*80 + s;
        float v0 = g_scratch[base + (size_t)i0 * PQ];
        float v1 = g_scratch[base + (size_t)i1 * PQ];
        S[e] = gm * (w0*v0 + w1*v1);
    }
    __syncthreads();

    // out[o][s] = sum_c Wf[o][c] * S[c][s] + bf[o]; Wf via float4 along c
    int s  = tid % 80;
    int og = tid / 80;   // o in [og*16, og*16+16)
    float acc[16];
    #pragma unroll
    for (int oo = 0; oo < 16; oo++) acc[oo] = 0.0f;

    #pragma unroll 4
    for (int c = 0; c < CC; c += 4) {
        float s0 = S[ c   *80 + s];
        float s1 = S[(c+1)*80 + s];
        float s2 = S[(c+2)*80 + s];
        float s3 = S[(c+3)*80 + s];
        #pragma unroll
        for (int oo = 0; oo < 16; oo++) {
            float4 wv = *(const float4*)&wfs[(og*16 + oo)*CC + c];
            acc[oo] += wv.x*s0 + wv.y*s1 + wv.z*s2 + wv.w*s3;
        }
    }
    #pragma unroll
    for (int oo = 0; oo < 16; oo++) {
        int o = og*16 + oo;
        out[(((size_t)n*CC + o)*TT + k) * PQ + quarter*80 + s] = acc[oo] + bfs[o];
    }
}

// ---------------- launch ----------------
extern "C" void kernel_launch(void* const* d_in, const int* in_sizes, int n_in,
                              void* d_out, int out_size) {
    const float* x   = (const float*)d_in[0];
    const float* px  = (const float*)d_in[1];
    const float* W1  = (const float*)d_in[2];
    const float* b1  = (const float*)d_in[3];
    const float* W2  = (const float*)d_in[4];
    const float* b2  = (const float*)d_in[5];
    const float* Wf  = (const float*)d_in[6];
    const float* bf  = (const float*)d_in[7];
    float* out = (float*)d_out;

    int write_params = (out_size >= OUT_TOTAL) ? 1 : 0;

    setup_kernel<<<1, 512>>>(px, W1, b1, W2, b2, out, write_params);

    dim3 g2(CT/2, NB);
    spatial_kernel<<<g2, 160>>>(x);

    dim3 g3(4, TT, NB);
    mix_kernel<<<g3, 320>>>(Wf, bf, out);
}

// round 3
// speedup vs baseline: 2.3891x; 1.4814x over previous
#include <cuda_runtime.h>
#include <cstdint>

// ---------------- problem constants ----------------
#define NB   16
#define CC   64
#define TT   30
#define HH   64
#define WW   44
#define PC   64
#define OUTH 16
#define OUTW 20
#define AOUTH 16
#define PQ   (OUTH*OUTW)    // 320
#define CT   (CC*TT)        // 1920
#define HW   (HH*WW)        // 2816
#define OUT_MAIN (NB*CC*TT*PQ)
#define OUT_TOTAL (OUT_MAIN + 7*NB)

#define W_RATE (10.0f/11.0f)
#define T_RATE 0.4f

// ---------------- device scratch (static, allocation-free) ----------------
__device__ float g_scratch[(size_t)NB*CT*PQ];      // 39.3 MB
__device__ float d_FxT[NB*WW*OUTW];                // [n][w][q]  (normalized)
__device__ float d_FyT[NB*HH*AOUTH];               // [n][h][p]  (normalized * gamma)
__device__ int   d_i0c[NB*TT];
__device__ int   d_i1c[NB*TT];
__device__ float d_w0[NB*TT];
__device__ float d_w1[NB*TT];

// ---------------- kernel 1: per-n MLP + params + transposed filter banks ----
// grid = NB blocks, 64 threads (2 warps)
__global__ void __launch_bounds__(64) setup_kernel(
        const float* __restrict__ px,
        const float* __restrict__ W1, const float* __restrict__ b1,
        const float* __restrict__ W2, const float* __restrict__ b2,
        float* __restrict__ out, int write_params) {
    int n    = blockIdx.x;
    int tid  = threadIdx.x;
    int lane = tid & 31;
    int wrp  = tid >> 5;

    __shared__ float hid[32];
    __shared__ float pv[7];
    __shared__ float s_dx, s_dy, s_s2, s_del, s_dt, s_dlt, s_gam;

    if (tid < 32) {
        float acc = b1[tid];
        #pragma unroll 8
        for (int i = 0; i < PC; i++) acc += px[n*PC + i] * W1[i*32 + tid];
        hid[tid] = tanhf(acc);
    }
    __syncthreads();

    if (tid < 7) {
        float acc = b2[tid];
        #pragma unroll
        for (int j = 0; j < 32; j++) acc += hid[j] * W2[j*7 + tid];
        pv[tid] = acc;
    }
    __syncthreads();

    if (tid == 0) {
        float dt0 = pv[0], dx0 = pv[1], dy0 = pv[2];
        float ls2 = pv[3], ldt = pv[4], ldl = pv[5], lg = pv[6];
        float dx    = tanhf(dx0) * 20.0f + 22.0f;   // atten_in_w/2 + anchor_x
        float dy    = tanhf(dy0) * 16.0f + 24.0f;   // atten_in_h/2 + anchor_y
        float s2    = expf(ls2);
        float delta = expf(ldl) * W_RATE;
        float gamma = 1.0f / (1.0f + expf(-lg));
        float dt    = tanhf(dt0) * 6.0f + 15.0f;    // atten_in_t/2 + anchor_t
        float dlt   = expf(ldt) * T_RATE;
        s_dx = dx; s_dy = dy; s_s2 = s2; s_del = delta;
        s_dt = dt; s_dlt = dlt; s_gam = gamma;
        if (write_params) {
            out[OUT_MAIN + 0*NB + n] = dt;
            out[OUT_MAIN + 1*NB + n] = dx;
            out[OUT_MAIN + 2*NB + n] = dy;
            out[OUT_MAIN + 3*NB + n] = s2;
            out[OUT_MAIN + 4*NB + n] = delta;
            out[OUT_MAIN + 5*NB + n] = dlt;
            out[OUT_MAIN + 6*NB + n] = gamma;
        }
    }
    __syncthreads();

    // temporal lerp indices/weights (30 per n)
    if (tid < TT) {
        float mu = s_dt + ((float)tid - 15.0f) * s_dlt;
        float fl = floorf(mu);
        float frac = mu - fl;
        int i0 = (int)fl;
        int i1 = i0 + 1;
        d_w0[n*TT + tid]  = (i0 >= 0 && i0 < TT) ? (1.0f - frac) : 0.0f;
        d_w1[n*TT + tid]  = (i1 >= 0 && i1 < TT) ? frac : 0.0f;
        d_i0c[n*TT + tid] = min(max(i0, 0), TT-1);
        d_i1c[n*TT + tid] = min(max(i1, 0), TT-1);
    }

    // filter rows: 0..19 -> Fx row q (len 44), 20..35 -> Fy row p (len 64).
    // warp-per-row with shfl reduction; store transposed.
    float inv2s = 1.0f / (2.0f * s_s2);
    for (int row = wrp; row < 36; row += 2) {
        float mu; int len;
        if (row < 20) { mu = s_dx + ((float)row - 10.0f) * s_del; len = WW; }
        else          { mu = s_dy + ((float)(row-20) - 8.0f) * s_del; len = HH; }
        float d0 = (float)lane - mu;
        float d1 = (float)(lane + 32) - mu;
        float v0 = (lane      < len) ? expf(-d0*d0*inv2s) : 0.0f;
        float v1 = (lane + 32 < len) ? expf(-d1*d1*inv2s) : 0.0f;
        float s = v0 + v1;
        #pragma unroll
        for (int o = 16; o > 0; o >>= 1) s += __shfl_xor_sync(0xffffffffu, s, o);
        float inv = 1.0f / fmaxf(s, 1e-8f);
        if (row < 20) {
            int q = row;
            if (lane < WW)  d_FxT[n*(WW*OUTW) + lane*OUTW + q]      = v0 * inv;
            if (lane+32 < WW) d_FxT[n*(WW*OUTW) + (lane+32)*OUTW + q] = v1 * inv;
        } else {
            int p = row - 20;
            float sc = inv * s_gam;     // fold gamma into Fy
            d_FyT[n*(HH*AOUTH) + lane*AOUTH + p]        = v0 * sc;
            d_FyT[n*(HH*AOUTH) + (lane+32)*AOUTH + p]   = v1 * sc;
        }
    }
}

// ---------------- kernel 2: spatial attention, Fy-first ----------------
// g[p][q] = sum_w ( sum_h Fy[p][h]*x[h][w] ) * Fx[q][w]
// 2 tiles/block, 176 threads. Phase1: 88 thr/tile, 4p x 2w regs.
// Phase2: 80 thr/tile, 2p x 2q regs.
__global__ void __launch_bounds__(176) spatial_kernel(const float* __restrict__ x) {
    __shared__ __align__(16) float xs[2*HW];          // [tile][h][w], natural stride 44
    __shared__ __align__(16) float fyT[HH*AOUTH];     // [h][p]
    __shared__ __align__(16) float fxT[WW*OUTW];      // [w][q]
    __shared__ __align__(16) float t1pT[2*WW*AOUTH];  // [tile][w][p]

    int n   = blockIdx.y;
    int ct0 = blockIdx.x * 2;
    int tid = threadIdx.x;

    // stage x: 2*2816 floats = 1408 float4, exactly 8 per thread
    {
        const float4* xp4 = (const float4*)(x + ((size_t)n*CT + ct0) * HW);
        float4* xs4 = (float4*)xs;
        #pragma unroll
        for (int r = 0; r < 8; r++) xs4[tid + r*176] = xp4[tid + r*176];
    }
    for (int i = tid; i < HH*AOUTH; i += 176) fyT[i] = d_FyT[n*(HH*AOUTH) + i];
    for (int i = tid; i < WW*OUTW;  i += 176) fxT[i] = d_FxT[n*(WW*OUTW) + i];
    __syncthreads();

    // phase 1: t1p[w][p] = sum_h Fy[p][h]*x[h][w]
    {
        int tile = tid / 88;
        int t    = tid - tile*88;
        int pg = t / 22, wg = t - pg*22;
        int p0 = pg*4, w0 = wg*2;
        float a00=0.f,a01=0.f,a10=0.f,a11=0.f,a20=0.f,a21=0.f,a30=0.f,a31=0.f;
        const float* xt = &xs[tile*HW];
        #pragma unroll 8
        for (int k = 0; k < HH; k++) {
            float4 fy = *(const float4*)&fyT[k*AOUTH + p0];
            float2 xv = *(const float2*)&xt[k*WW + w0];
            a00 += fy.x*xv.x; a01 += fy.x*xv.y;
            a10 += fy.y*xv.x; a11 += fy.y*xv.y;
            a20 += fy.z*xv.x; a21 += fy.z*xv.y;
            a30 += fy.w*xv.x; a31 += fy.w*xv.y;
        }
        float* tp = &t1pT[tile*(WW*AOUTH)];
        *(float4*)&tp[ w0   *AOUTH + p0] = make_float4(a00, a10, a20, a30);
        *(float4*)&tp[(w0+1)*AOUTH + p0] = make_float4(a01, a11, a21, a31);
    }
    __syncthreads();

    // phase 2: g[p][q] = sum_w t1p[w][p] * Fx[q][w]
    if (tid < 160) {
        int tile = tid / 80;
        int t    = tid - tile*80;
        int p0 = (t / 10) * 2;
        int q0 = (t % 10) * 2;
        float b00=0.f,b01=0.f,b10=0.f,b11=0.f;
        const float* tp = &t1pT[tile*(WW*AOUTH)];
        #pragma unroll 4
        for (int k = 0; k < WW; k++) {
            float2 tv = *(const float2*)&tp[k*AOUTH + p0];
            float2 fx = *(const float2*)&fxT[k*OUTW + q0];
            b00 += tv.x*fx.x; b01 += tv.x*fx.y;
            b10 += tv.y*fx.x; b11 += tv.y*fx.y;
        }
        float* gp = &g_scratch[((size_t)n*CT + ct0 + tile) * PQ];
        *(float2*)&gp[ p0   *OUTW + q0] = make_float2(b00, b01);
        *(float2*)&gp[(p0+1)*OUTW + q0] = make_float2(b10, b11);
    }
}

// ---------------- kernel 3: temporal lerp + channel mix GEMM ----------------
__global__ void __launch_bounds__(320) mix_kernel(const float* __restrict__ Wf,
                                                  const float* __restrict__ bf,
                                                  float* __restrict__ out) {
    __shared__ float wfs[CC*CC];
    __shared__ float S[CC*80];        // [c][s] (gamma already folded into g)
    __shared__ float bfs[CC];

    int quarter = blockIdx.x;
    int k = blockIdx.y;
    int n = blockIdx.z;
    int tid = threadIdx.x;

    for (int i = tid; i < CC*CC; i += 320) wfs[i] = Wf[i];
    if (tid < CC) bfs[tid] = bf[tid];

    int   i0 = d_i0c[n*TT + k];
    int   i1 = d_i1c[n*TT + k];
    float w0 = d_w0[n*TT + k];
    float w1 = d_w1[n*TT + k];

    #pragma unroll
    for (int r = 0; r < 16; r++) {
        int e = tid + r*320;
        int c = e / 80, s = e - c*80;
        size_t base = ((size_t)(n*CC + c) * TT) * PQ + quarter*80 + s;
        float v0 = g_scratch[base + (size_t)i0 * PQ];
        float v1 = g_scratch[base + (size_t)i1 * PQ];
        S[e] = w0*v0 + w1*v1;
    }
    __syncthreads();

    int s  = tid % 80;
    int og = tid / 80;
    float acc[16];
    #pragma unroll
    for (int oo = 0; oo < 16; oo++) acc[oo] = 0.0f;

    #pragma unroll 4
    for (int c = 0; c < CC; c += 4) {
        float s0 = S[ c   *80 + s];
        float s1 = S[(c+1)*80 + s];
        float s2 = S[(c+2)*80 + s];
        float s3 = S[(c+3)*80 + s];
        #pragma unroll
        for (int oo = 0; oo < 16; oo++) {
            float4 wv = *(const float4*)&wfs[(og*16 + oo)*CC + c];
            acc[oo] += wv.x*s0 + wv.y*s1 + wv.z*s2 + wv.w*s3;
        }
    }
    #pragma unroll
    for (int oo = 0; oo < 16; oo++) {
        int o = og*16 + oo;
        out[(((size_t)n*CC + o)*TT + k) * PQ + quarter*80 + s] = acc[oo] + bfs[o];
    }
}

// ---------------- launch ----------------
extern "C" void kernel_launch(void* const* d_in, const int* in_sizes, int n_in,
                              void* d_out, int out_size) {
    const float* x   = (const float*)d_in[0];
    const float* px  = (const float*)d_in[1];
    const float* W1  = (const float*)d_in[2];
    const float* b1  = (const float*)d_in[3];
    const float* W2  = (const float*)d_in[4];
    const float* b2  = (const float*)d_in[5];
    const float* Wf  = (const float*)d_in[6];
    const float* bf  = (const float*)d_in[7];
    float* out = (float*)d_out;

    int write_params = (out_size >= OUT_TOTAL) ? 1 : 0;

    setup_kernel<<<NB, 64>>>(px, W1, b1, W2, b2, out, write_params);

    dim3 g2(CT/2, NB);
    spatial_kernel<<<g2, 176>>>(x);

    dim3 g3(4, TT, NB);
    mix_kernel<<<g3, 320>>>(Wf, bf, out);
}